// round 8
// baseline (speedup 1.0000x reference)
#include <cuda_runtime.h>
#include <cstdint>

// out[b,l,h] = data[b,l,h] * mask(b,l)
//   mask = l < a_end      -> 1 - (a_end - l)/C
//          elif l < s_len -> 1 - (l - a_idx)/C
//          else           -> 0
// B=512, L=512, H=100, C=40.
// Index arrays are int32 (JAX x32 downcasts the requested int64).
//
// Dead-row skip (mask==0 -> store zeros, never read data) cuts read traffic
// ~2x. With DRAM no longer saturated the kernel is latency-bound, so KPT=8
// two-phase (masks first from cache-resident scalars, then 8 predicated
// front-batched stream loads) doubles live MLP per warp.

#define B_DIM 512
#define L_DIM 512
#define H_DIM 100
#define VEC_PER_ROW (H_DIM / 4)                      // 25
#define TOTAL_VEC (B_DIM * L_DIM * VEC_PER_ROW)      // 6,553,600
#define KPT 8
#define THREADS 256
#define BLOCKS (TOTAL_VEC / (THREADS * KPT))         // 3200, exact

#define C_INV (1.0f / 40.0f)

__device__ __forceinline__ float row_mask(int l, int a_idx, int a_end, int s_len)
{
    float i_f = (float)l;
    if (l < a_end)  return 1.0f - ((float)a_end - i_f) * C_INV;
    if (l < s_len)  return 1.0f - (i_f - (float)a_idx) * C_INV;
    return 0.0f;
}

__global__ __launch_bounds__(THREADS) void mask_mul_kernel(
    const float4* __restrict__ data,
    const int* __restrict__ aspect_index,
    const int* __restrict__ aspect_len,
    const int* __restrict__ sents_len,
    float4* __restrict__ out)
{
    int base = blockIdx.x * (THREADS * KPT) + threadIdx.x;

    // Phase 1: masks from cache-resident index arrays (no stream traffic).
    float m[KPT];
#pragma unroll
    for (int k = 0; k < KPT; k++) {
        int idx = base + k * THREADS;
        int row = idx / VEC_PER_ROW;         // b*L + l  (const div -> mulhi)
        int b = row >> 9;                    // / L_DIM
        int l = row & (L_DIM - 1);
        int a_idx = __ldg(&aspect_index[b]);
        int a_end = a_idx + __ldg(&aspect_len[b]);
        int s_len = __ldg(&sents_len[b]);
        m[k] = row_mask(l, a_idx, a_end, s_len);
    }

    // Phase 2: predicated front-batched stream loads (live MLP up to 8).
    float4 v[KPT];
#pragma unroll
    for (int k = 0; k < KPT; k++) {
        if (m[k] != 0.0f) {
            v[k] = data[base + k * THREADS];
        } else {
            v[k] = make_float4(0.0f, 0.0f, 0.0f, 0.0f);
        }
    }

    // Phase 3: scale + store.
#pragma unroll
    for (int k = 0; k < KPT; k++) {
        v[k].x *= m[k]; v[k].y *= m[k]; v[k].z *= m[k]; v[k].w *= m[k];
        out[base + k * THREADS] = v[k];
    }
}

extern "C" void kernel_launch(void* const* d_in, const int* in_sizes, int n_in,
                              void* d_out, int out_size)
{
    const float4* data = (const float4*)d_in[0];
    const int*    aidx = (const int*)d_in[1];
    const int*    alen = (const int*)d_in[2];
    const int*    slen = (const int*)d_in[3];
    float4* out = (float4*)d_out;

    mask_mul_kernel<<<BLOCKS, THREADS>>>(data, aidx, alen, slen, out);
}

// round 9
// speedup vs baseline: 1.0229x; 1.0229x over previous
#include <cuda_runtime.h>
#include <cstdint>

// out[b,l,h] = data[b,l,h] * mask(b,l)
//   mask = l < a_end      -> 1 - (a_end - l)/C
//          elif l < s_len -> 1 - (l - a_idx)/C
//          else           -> 0
// B=512, L=512, H=100, C=40.
// Index arrays are int32 (JAX x32 downcasts the requested int64).
//
// Dead-row skip (mask==0 -> never read data) cuts read traffic ~2x; the
// kernel is then latency-bound. KPT=8 with __launch_bounds__(256,4) gives
// ptxas a 64-reg budget so all 8 predicated stream loads stay front-batched
// (R8 failed because ptxas capped at 30 regs and serialized them).

#define B_DIM 512
#define L_DIM 512
#define H_DIM 100
#define VEC_PER_ROW (H_DIM / 4)                      // 25
#define TOTAL_VEC (B_DIM * L_DIM * VEC_PER_ROW)      // 6,553,600
#define KPT 8
#define THREADS 256
#define BLOCKS (TOTAL_VEC / (THREADS * KPT))         // 3200, exact

#define C_INV (1.0f / 40.0f)

__device__ __forceinline__ float row_mask(int l, int a_idx, int a_end, int s_len)
{
    float i_f = (float)l;
    if (l < a_end)  return 1.0f - ((float)a_end - i_f) * C_INV;
    if (l < s_len)  return 1.0f - (i_f - (float)a_idx) * C_INV;
    return 0.0f;
}

__global__ __launch_bounds__(THREADS, 4) void mask_mul_kernel(
    const float4* __restrict__ data,
    const int* __restrict__ aspect_index,
    const int* __restrict__ aspect_len,
    const int* __restrict__ sents_len,
    float4* __restrict__ out)
{
    int base = blockIdx.x * (THREADS * KPT) + threadIdx.x;

    // Phase 1: masks from cache-resident index arrays (no stream traffic).
    float m[KPT];
#pragma unroll
    for (int k = 0; k < KPT; k++) {
        int idx = base + k * THREADS;
        int row = idx / VEC_PER_ROW;         // b*L + l  (const div -> mulhi)
        int b = row >> 9;                    // / L_DIM
        int l = row & (L_DIM - 1);
        int a_idx = __ldg(&aspect_index[b]);
        int a_end = a_idx + __ldg(&aspect_len[b]);
        int s_len = __ldg(&sents_len[b]);
        m[k] = row_mask(l, a_idx, a_end, s_len);
    }

    // Phase 2: predicated front-batched stream loads (live MLP up to 8).
    float4 v[KPT];
#pragma unroll
    for (int k = 0; k < KPT; k++) {
        if (m[k] != 0.0f) {
            v[k] = data[base + k * THREADS];
        } else {
            v[k] = make_float4(0.0f, 0.0f, 0.0f, 0.0f);
        }
    }

    // Phase 3: scale + store.
#pragma unroll
    for (int k = 0; k < KPT; k++) {
        v[k].x *= m[k]; v[k].y *= m[k]; v[k].z *= m[k]; v[k].w *= m[k];
        out[base + k * THREADS] = v[k];
    }
}

extern "C" void kernel_launch(void* const* d_in, const int* in_sizes, int n_in,
                              void* d_out, int out_size)
{
    const float4* data = (const float4*)d_in[0];
    const int*    aidx = (const int*)d_in[1];
    const int*    alen = (const int*)d_in[2];
    const int*    slen = (const int*)d_in[3];
    float4* out = (float4*)d_out;

    mask_mul_kernel<<<BLOCKS, THREADS>>>(data, aidx, alen, slen, out);
}

// round 10
// speedup vs baseline: 1.0789x; 1.0548x over previous
#include <cuda_runtime.h>
#include <cstdint>

// out[b,l,h] = data[b,l,h] * mask(b,l)
//   mask = l < a_end      -> 1 - (a_end - l)/C
//          elif l < s_len -> 1 - (l - a_idx)/C
//          else           -> 0
// B=512, L=512, H=100, C=40.
// Index arrays are int32 (JAX x32 downcasts the requested int64).
//
// R7 structure (KPT=4, batched predicated loads, dead-row read skip) +
// block-shared row masks: a block spans <=42 rows, so 44 threads compute
// masks into smem once; the hot loop is 1 LDS + 1 predicated LDG + 1 STG
// per element instead of 4 LDG + 1 STG + full mask recompute.

#define B_DIM 512
#define L_DIM 512
#define H_DIM 100
#define VEC_PER_ROW (H_DIM / 4)                      // 25
#define TOTAL_VEC (B_DIM * L_DIM * VEC_PER_ROW)      // 6,553,600
#define KPT 4
#define THREADS 256
#define VPB (THREADS * KPT)                          // 1024 vec per block
#define BLOCKS (TOTAL_VEC / VPB)                     // 6400, exact
#define NROWS_SMEM 44                                // ceil(1024/25)+safety

#define C_INV (1.0f / 40.0f)

__global__ __launch_bounds__(THREADS) void mask_mul_kernel(
    const float4* __restrict__ data,
    const int* __restrict__ aspect_index,
    const int* __restrict__ aspect_len,
    const int* __restrict__ sents_len,
    float4* __restrict__ out)
{
    __shared__ float smask[NROWS_SMEM];

    int v0 = blockIdx.x * VPB;
    int r0 = v0 / VEC_PER_ROW;                       // first row this block touches
    int tid = threadIdx.x;

    // Phase 0: 44 threads compute this block's row masks into smem.
    if (tid < NROWS_SMEM) {
        int r = r0 + tid;
        float m = 0.0f;
        if (r < B_DIM * L_DIM) {
            int b = r >> 9;                          // / L_DIM
            int l = r & (L_DIM - 1);
            int a_idx = __ldg(&aspect_index[b]);
            int a_end = a_idx + __ldg(&aspect_len[b]);
            int s_len = __ldg(&sents_len[b]);
            float i_f = (float)l;
            if (l < a_end)      m = 1.0f - ((float)a_end - i_f) * C_INV;
            else if (l < s_len) m = 1.0f - (i_f - (float)a_idx) * C_INV;
        }
        smask[tid] = m;
    }
    __syncthreads();

    // Phase 1: masks from smem (row-local index).
    float m[KPT];
#pragma unroll
    for (int k = 0; k < KPT; k++) {
        int idx = v0 + tid + k * THREADS;
        int row = idx / VEC_PER_ROW;                 // const div -> mulhi
        m[k] = smask[row - r0];
    }

    // Phase 2: predicated front-batched stream loads (skip dead rows).
    float4 v[KPT];
#pragma unroll
    for (int k = 0; k < KPT; k++) {
        if (m[k] != 0.0f) {
            v[k] = data[v0 + tid + k * THREADS];
        } else {
            v[k] = make_float4(0.0f, 0.0f, 0.0f, 0.0f);
        }
    }

    // Phase 3: scale + store.
#pragma unroll
    for (int k = 0; k < KPT; k++) {
        v[k].x *= m[k]; v[k].y *= m[k]; v[k].z *= m[k]; v[k].w *= m[k];
        out[v0 + tid + k * THREADS] = v[k];
    }
}

extern "C" void kernel_launch(void* const* d_in, const int* in_sizes, int n_in,
                              void* d_out, int out_size)
{
    const float4* data = (const float4*)d_in[0];
    const int*    aidx = (const int*)d_in[1];
    const int*    alen = (const int*)d_in[2];
    const int*    slen = (const int*)d_in[3];
    float4* out = (float4*)d_out;

    mask_mul_kernel<<<BLOCKS, THREADS>>>(data, aidx, alen, slen, out);
}